// round 15
// baseline (speedup 1.0000x reference)
#include <cuda_runtime.h>

#define HH 256
#define WW 256
#define PP 512
// ALPHA = -5.0f, 1/ALPHA = -0.2f

typedef unsigned long long ull;

__device__ float g_sum[PP];          // zero-init at load; reset by epilogue
__device__ float g_numA[HH];
__device__ float g_denA[HH];
__device__ int   g_ctr = 0;

__device__ __forceinline__ float fsqrt_a(float x) {
    float r; asm("sqrt.approx.f32 %0, %1;" : "=f"(r) : "f"(x)); return r;
}
__device__ __forceinline__ float frcp_a(float x) {
    float r; asm("rcp.approx.f32 %0, %1;" : "=f"(r) : "f"(x)); return r;
}
__device__ __forceinline__ float fex2_a(float x) {
    float r; asm("ex2.approx.f32 %0, %1;" : "=f"(r) : "f"(x)); return r;
}
__device__ __forceinline__ float flg2_a(float x) {
    float r; asm("lg2.approx.f32 %0, %1;" : "=f"(r) : "f"(x)); return r;
}
__device__ __forceinline__ ull pk2(float lo, float hi) {
    ull r; asm("mov.b64 %0, {%1, %2};" : "=l"(r) : "f"(lo), "f"(hi)); return r;
}
__device__ __forceinline__ void upk2(ull v, float& lo, float& hi) {
    asm("mov.b64 {%0, %1}, %2;" : "=f"(lo), "=f"(hi) : "l"(v));
}
__device__ __forceinline__ ull f2add(ull a, ull b) {
    ull r; asm("add.rn.f32x2 %0, %1, %2;" : "=l"(r) : "l"(a), "l"(b)); return r;
}
__device__ __forceinline__ ull f2mul(ull a, ull b) {
    ull r; asm("mul.rn.f32x2 %0, %1, %2;" : "=l"(r) : "l"(a), "l"(b)); return r;
}
__device__ __forceinline__ ull f2fma(ull a, ull b, ull c) {
    ull r; asm("fma.rn.f32x2 %0, %1, %2, %3;" : "=l"(r) : "l"(a), "l"(b), "l"(c)); return r;
}

// ---------------------------------------------------------------------------
// 128 blocks x 1024 threads (one wave). Block b owns rows 2b, 2b+1.
// Fused loop: phase A (min-shift quadratic: min_j fma(c1,x,c0), +x^2 at end)
// + phase B (packed s/dy chain, paired MUFU rcp: 3 MUFU / 2 pixels).
// ---------------------------------------------------------------------------
__global__ __launch_bounds__(1024, 1) void k_all(const float* __restrict__ hm,
                                                 const float* __restrict__ pts,
                                                 float* __restrict__ out) {
    __shared__ float4 preA[2][PP / 2];   // per row: (c1_0, c1_1, c0_0, c0_1)
    __shared__ float4 preB[2][PP / 2];   // per row: (-px0,-px1,dxs0,dxs1) EXACT
    __shared__ float  s_hm[2][WW];       // per row: raw h
    __shared__ float4 s_hb[2][WW / 2];   // per row: (h0,h1,bb0,bb1)
    __shared__ float  s_min[2][2][256];  // per row, per point-half: shifted min
    __shared__ float  s_red[32], s_red2[32];
    __shared__ float  s_M;

    int tid  = threadIdx.x;              // 0..1023
    int row  = tid >> 9;                 // 0/1 within the row pair
    int t    = tid & 511;                // point index within row
    int y    = blockIdx.x * 2 + row;

    // ---- per-row point tables + corner max (separable -> grid corner) ------
    float py = pts[2 * t], px = pts[2 * t + 1];
    float dxv = (float)y - py;
    float dxs = dxv * dxv;
    {
        int cell = t >> 1, par = t & 1;
        float* pa = (float*)preA[row];
        float* pb = (float*)preB[row];
        pa[cell * 4 + par]     = -2.0f * px;             // c1
        pa[cell * 4 + 2 + par] = fmaf(px, px, dxs);      // c0 = px^2 + dxs
        pb[cell * 4 + par]     = -px;                    // exact np
        pb[cell * 4 + 2 + par] = dxs;                    // exact dxs
    }
    float my = fmaxf(py, 255.0f - py);
    float mx = fmaxf(px, 255.0f - px);
    float lmax = fmaf(my, my, mx * mx);

    float h = 0.f;
    if (t < WW) {
        h = hm[y * WW + t];
        s_hm[row][t] = h;
    }

    int warp = tid >> 5, lane = tid & 31;
    for (int o = 16; o > 0; o >>= 1)
        lmax = fmaxf(lmax, __shfl_down_sync(0xffffffffu, lmax, o));
    if (lane == 0) s_red[warp] = lmax;
    __syncthreads();
    if (tid == 0) {
        float m = s_red[0];
#pragma unroll
        for (int i = 1; i < 32; ++i) m = fmaxf(m, s_red[i]);
        s_M = sqrtf(m);
    }
    __syncthreads();
    float M = s_M;

    // ---- (h, bb) pixel-pair quads (t < 128 per row) -------------------------
    if (t < WW / 2) {
        float h0 = s_hm[row][2 * t], h1 = s_hm[row][2 * t + 1];
        s_hb[row][t] = make_float4(h0, h1, fmaf(-h0, M, M), fmaf(-h1, M, M));
    }
    __syncthreads();

    // ---------------- fused main loop ----------------------------------------
    int p  = tid & 255;                  // phase-A pixel
    int hp = (tid >> 8) & 1;             // phase-A point half
    const float4* ptabA = &preA[row][hp * 128];
    const float*  prefs = (const float*)preB[row];
    int base = (t >> 1) * 4 + (t & 1);
    float np   = prefs[base];            // -px for point t (exact)
    float dxsE = prefs[base + 2];        // (y-py)^2 (exact)
    const float4* hb = s_hb[row];

    float xf  = (float)p;
    float m0  = 3.4e38f, m1 = 3.4e38f;
    ull DY   = pk2(np, np + 1.0f);       // dy at pixels 0,1 (exact += 2)
    ull DXS  = pk2(dxsE, dxsE);
    ull TWO2 = pk2(2.0f, 2.0f);
    ull SACC = 0;

#pragma unroll 4
    for (int k = 0; k < 128; ++k) {
        // phase A: two points of quad k vs pixel p (min-shift form)
        float4 qa = ptabA[k];            // (c1_0, c1_1, c0_0, c0_1)
        m0 = fminf(m0, fmaf(qa.x, xf, qa.z));
        m1 = fminf(m1, fmaf(qa.y, xf, qa.w));

        // phase B: point t vs pixels 2k, 2k+1
        float4 qb = hb[k];               // (h0,h1,bb0,bb1)
        ull S = f2fma(DY, DY, DXS);      // packed s = dy^2 + dxs (exact)
        float sA, sB; upk2(S, sA, sB);
        float dA = fsqrt_a(sA);          // MUFU sqrt x2
        float dB = fsqrt_a(sB);
        float wA = fmaf(qb.x, dA, qb.z); // w = h*d + (1-h)*M  (> 0)
        float wB = fmaf(qb.y, dB, qb.w);
        float r  = frcp_a(wA * wB);      // ONE MUFU rcp serves both pixels
        float qA = wB * r;               // 1/wA
        float qB = wA * r;               // 1/wB
        ull Y  = pk2(qA, qB);
        ull Q2 = f2mul(Y, Y);
        ull Q4 = f2mul(Q2, Q2);
        SACC = f2fma(Q4, Y, SACC);       // += w^-5
        DY = f2add(DY, TWO2);
    }
    s_min[row][hp][p] = fminf(m0, m1);   // still missing +x^2 (added below)
    float SA, SB; upk2(SACC, SA, SB);
    atomicAdd(&g_sum[t], SA + SB);
    __syncthreads();

    // ---------------- term-1 reduction (needs all s_min) ---------------------
    {
        float t1 = 0.f, ah = 0.f;
        if (hp == 0) {                   // these threads hold h for pixel p
            float xf2 = (float)p * (float)p;
            float mins = fminf(s_min[row][0][p], s_min[row][1][p]) + xf2;
            mins = fmaxf(mins, 0.0f);    // clamp cancellation error
            t1 = h * fsqrt_a(mins);
            ah = fabsf(h);
        }
        for (int o = 16; o > 0; o >>= 1) {
            t1 += __shfl_down_sync(0xffffffffu, t1, o);
            ah += __shfl_down_sync(0xffffffffu, ah, o);
        }
        if (lane == 0) { s_red[warp] = t1; s_red2[warp] = ah; }
    }
    __syncthreads();
    if (t == 0) {                        // one finisher per row
        int w0 = row * 16;               // row's hp==0 warps
        float a = 0.f, b = 0.f;
#pragma unroll
        for (int i = 0; i < 8; ++i) { a += s_red[w0 + i]; b += s_red2[w0 + i]; }
        g_numA[y] = a;
        g_denA[y] = b;
    }

    // ---------------- last-block epilogue ------------------------------------
    __shared__ int s_last;
    __threadfence();
    __syncthreads();
    if (tid == 0) s_last = (atomicAdd(&g_ctr, 1) == (int)gridDim.x - 1);
    __syncthreads();
    if (!s_last) return;

    float* red = (float*)preA;           // reuse smem
    float* r2  = (float*)s_hm;
    float* r3  = (float*)s_min;
    if (tid < PP) {
        float Ssum = g_sum[tid];
        // mean^(1/ALPHA) via MUFU lg2/ex2
        red[tid] = fex2_a(-0.2f * flg2_a(Ssum * (1.0f / (HH * WW))));
        g_sum[tid] = 0.f;                // reset for next replay
    }
    if (tid < HH) { r2[tid] = g_numA[tid]; r3[tid] = g_denA[tid]; }
    __syncthreads();
    for (int o = 256; o > 0; o >>= 1) {
        if (tid < o) red[tid] += red[tid + o];
        __syncthreads();
    }
    for (int o = 128; o > 0; o >>= 1) {
        if (tid < o) { r2[tid] += r2[tid + o]; r3[tid] += r3[tid + o]; }
        __syncthreads();
    }
    if (tid == 0) {
        out[0] = r2[0] / r3[0] + red[0] * (1.0f / PP);
        g_ctr = 0;                       // reset for next replay
    }
}

extern "C" void kernel_launch(void* const* d_in, const int* in_sizes, int n_in,
                              void* d_out, int out_size) {
    (void)in_sizes; (void)n_in; (void)out_size;
    const float* hm  = (const float*)d_in[0];   // heat_map (256*256)
    const float* pts = (const float*)d_in[1];   // points   (512*2)
    float* out = (float*)d_out;

    k_all<<<HH / 2, 1024>>>(hm, pts, out);
}

// round 16
// speedup vs baseline: 1.0229x; 1.0229x over previous
#include <cuda_runtime.h>

#define HH 256
#define WW 256
#define PP 512
// ALPHA = -5.0f, 1/ALPHA = -0.2f

__device__ float g_sum[PP];          // zero-init at load; reset by epilogue
__device__ float g_numA[HH];
__device__ float g_denA[HH];
__device__ int   g_ctr = 0;

__device__ __forceinline__ float fsqrt_a(float x) {
    float r; asm("sqrt.approx.f32 %0, %1;" : "=f"(r) : "f"(x)); return r;
}
__device__ __forceinline__ float frcp_a(float x) {
    float r; asm("rcp.approx.f32 %0, %1;" : "=f"(r) : "f"(x)); return r;
}
__device__ __forceinline__ float fex2_a(float x) {
    float r; asm("ex2.approx.f32 %0, %1;" : "=f"(r) : "f"(x)); return r;
}
__device__ __forceinline__ float flg2_a(float x) {
    float r; asm("lg2.approx.f32 %0, %1;" : "=f"(r) : "f"(x)); return r;
}

// ---------------------------------------------------------------------------
// 128 blocks x 1024 threads (one wave). Block b owns rows 2b, 2b+1.
// FULLY SCALAR fused loop (no f32x2, no pack/unpack marshaling):
//   phase A: min-shift quadratic min_j fma(c1_j, x, c0_j), +x^2 at the end
//   phase B: exact dy-recurrence soft power sums, paired MUFU rcp
// ---------------------------------------------------------------------------
__global__ __launch_bounds__(1024, 1) void k_all(const float* __restrict__ hm,
                                                 const float* __restrict__ pts,
                                                 float* __restrict__ out) {
    __shared__ float4 preA[2][PP / 2];   // per row: (c1_0, c1_1, c0_0, c0_1)
    __shared__ float4 preB[2][PP / 2];   // per row: (-px0,-px1,dxs0,dxs1) EXACT
    __shared__ float  s_hm[2][WW];       // per row: raw h
    __shared__ float4 s_hb[2][WW / 2];   // per row: (h0,h1,bb0,bb1)
    __shared__ float  s_min[2][2][256];  // per row, per point-half: shifted min
    __shared__ float  s_red[32], s_red2[32];
    __shared__ float  s_M;

    int tid  = threadIdx.x;              // 0..1023
    int row  = tid >> 9;                 // 0/1 within the row pair
    int t    = tid & 511;                // point index within row
    int y    = blockIdx.x * 2 + row;

    // ---- per-row point tables + corner max (separable -> grid corner) ------
    float py = pts[2 * t], px = pts[2 * t + 1];
    float dxv = (float)y - py;
    float dxs = dxv * dxv;
    {
        int cell = t >> 1, par = t & 1;
        float* pa = (float*)preA[row];
        float* pb = (float*)preB[row];
        pa[cell * 4 + par]     = -2.0f * px;             // c1
        pa[cell * 4 + 2 + par] = fmaf(px, px, dxs);      // c0 = px^2 + dxs
        pb[cell * 4 + par]     = -px;                    // exact np
        pb[cell * 4 + 2 + par] = dxs;                    // exact dxs
    }
    float my = fmaxf(py, 255.0f - py);
    float mx = fmaxf(px, 255.0f - px);
    float lmax = fmaf(my, my, mx * mx);

    float h = 0.f;
    if (t < WW) {
        h = hm[y * WW + t];
        s_hm[row][t] = h;
    }

    int warp = tid >> 5, lane = tid & 31;
    for (int o = 16; o > 0; o >>= 1)
        lmax = fmaxf(lmax, __shfl_down_sync(0xffffffffu, lmax, o));
    if (lane == 0) s_red[warp] = lmax;
    __syncthreads();
    if (tid == 0) {
        float m = s_red[0];
#pragma unroll
        for (int i = 1; i < 32; ++i) m = fmaxf(m, s_red[i]);
        s_M = sqrtf(m);
    }
    __syncthreads();
    float M = s_M;

    // ---- (h, bb) pixel-pair quads (t < 128 per row) -------------------------
    if (t < WW / 2) {
        float h0 = s_hm[row][2 * t], h1 = s_hm[row][2 * t + 1];
        s_hb[row][t] = make_float4(h0, h1, fmaf(-h0, M, M), fmaf(-h1, M, M));
    }
    __syncthreads();

    // ---------------- fused main loop (all scalar) ---------------------------
    int p  = tid & 255;                  // phase-A pixel
    int hp = (tid >> 8) & 1;             // phase-A point half
    const float4* ptabA = &preA[row][hp * 128];
    const float*  prefs = (const float*)preB[row];
    int base = (t >> 1) * 4 + (t & 1);
    float np   = prefs[base];            // -px for point t (exact)
    float dxsE = prefs[base + 2];        // (y-py)^2 (exact)
    const float4* hb = s_hb[row];

    float xf  = (float)p;
    float m0  = 3.4e38f, m1 = 3.4e38f;
    float dyA = np;                      // dy at even pixel (exact += 2 chain)
    float dyB = np + 1.0f;               // dy at odd pixel
    float accA = 0.f, accB = 0.f;

#pragma unroll 8
    for (int k = 0; k < 128; ++k) {
        // phase A: two points of quad k vs pixel p (min-shift form)
        float4 qa = ptabA[k];            // (c1_0, c1_1, c0_0, c0_1)
        m0 = fminf(m0, fmaf(qa.x, xf, qa.z));
        m1 = fminf(m1, fmaf(qa.y, xf, qa.w));

        // phase B: point t vs pixels 2k, 2k+1
        float4 qb = hb[k];               // (h0,h1,bb0,bb1)
        float sA = fmaf(dyA, dyA, dxsE); // exact, always > 0
        float sB = fmaf(dyB, dyB, dxsE);
        float dA = fsqrt_a(sA);          // MUFU sqrt x2
        float dB = fsqrt_a(sB);
        float wA = fmaf(qb.x, dA, qb.z); // w = h*d + (1-h)*M  (> 0)
        float wB = fmaf(qb.y, dB, qb.w);
        float r  = frcp_a(wA * wB);      // ONE MUFU rcp serves both pixels
        float qA = wB * r;               // 1/wA
        float qB = wA * r;               // 1/wB
        float qA2 = qA * qA, qB2 = qB * qB;
        float qA4 = qA2 * qA2, qB4 = qB2 * qB2;
        accA = fmaf(qA4, qA, accA);      // += w^-5
        accB = fmaf(qB4, qB, accB);
        dyA += 2.0f;
        dyB += 2.0f;
    }
    s_min[row][hp][p] = fminf(m0, m1);   // still missing +x^2 (added below)
    atomicAdd(&g_sum[t], accA + accB);
    __syncthreads();

    // ---------------- term-1 reduction (needs all s_min) ---------------------
    {
        float t1 = 0.f, ah = 0.f;
        if (hp == 0) {                   // these threads hold h for pixel p
            float xf2 = (float)p * (float)p;
            float mins = fminf(s_min[row][0][p], s_min[row][1][p]) + xf2;
            mins = fmaxf(mins, 0.0f);    // clamp cancellation error
            t1 = h * fsqrt_a(mins);
            ah = fabsf(h);
        }
        for (int o = 16; o > 0; o >>= 1) {
            t1 += __shfl_down_sync(0xffffffffu, t1, o);
            ah += __shfl_down_sync(0xffffffffu, ah, o);
        }
        if (lane == 0) { s_red[warp] = t1; s_red2[warp] = ah; }
    }
    __syncthreads();
    if (t == 0) {                        // one finisher per row
        int w0 = row * 16;               // row's hp==0 warps
        float a = 0.f, b = 0.f;
#pragma unroll
        for (int i = 0; i < 8; ++i) { a += s_red[w0 + i]; b += s_red2[w0 + i]; }
        g_numA[y] = a;
        g_denA[y] = b;
    }

    // ---------------- last-block epilogue ------------------------------------
    __shared__ int s_last;
    __threadfence();
    __syncthreads();
    if (tid == 0) s_last = (atomicAdd(&g_ctr, 1) == (int)gridDim.x - 1);
    __syncthreads();
    if (!s_last) return;

    float* red = (float*)preA;           // reuse smem
    float* r2  = (float*)s_hm;
    float* r3  = (float*)s_min;
    if (tid < PP) {
        float Ssum = g_sum[tid];
        // mean^(1/ALPHA) via MUFU lg2/ex2
        red[tid] = fex2_a(-0.2f * flg2_a(Ssum * (1.0f / (HH * WW))));
        g_sum[tid] = 0.f;                // reset for next replay
    }
    if (tid < HH) { r2[tid] = g_numA[tid]; r3[tid] = g_denA[tid]; }
    __syncthreads();
    for (int o = 256; o > 0; o >>= 1) {
        if (tid < o) red[tid] += red[tid + o];
        __syncthreads();
    }
    for (int o = 128; o > 0; o >>= 1) {
        if (tid < o) { r2[tid] += r2[tid + o]; r3[tid] += r3[tid + o]; }
        __syncthreads();
    }
    if (tid == 0) {
        out[0] = r2[0] / r3[0] + red[0] * (1.0f / PP);
        g_ctr = 0;                       // reset for next replay
    }
}

extern "C" void kernel_launch(void* const* d_in, const int* in_sizes, int n_in,
                              void* d_out, int out_size) {
    (void)in_sizes; (void)n_in; (void)out_size;
    const float* hm  = (const float*)d_in[0];   // heat_map (256*256)
    const float* pts = (const float*)d_in[1];   // points   (512*2)
    float* out = (float*)d_out;

    k_all<<<HH / 2, 1024>>>(hm, pts, out);
}

// round 17
// speedup vs baseline: 1.1509x; 1.1251x over previous
#include <cuda_runtime.h>

#define HH 256
#define WW 256
#define PP 512
#define RW 72                        // phase-B x-window radius (error budget 5x)
// ALPHA = -5.0f, 1/ALPHA = -0.2f

__device__ float2 g_spts[PP];        // points sorted by px (k_prep)
__device__ float  g_M;               // global max distance
__device__ float  g_sum[PP];         // zero-init at load; reset by epilogue
__device__ float  g_numA[HH];
__device__ float  g_denA[HH];
__device__ int    g_ctr = 0;

__device__ __forceinline__ float fsqrt_a(float x) {
    float r; asm("sqrt.approx.f32 %0, %1;" : "=f"(r) : "f"(x)); return r;
}
__device__ __forceinline__ float frcp_a(float x) {
    float r; asm("rcp.approx.f32 %0, %1;" : "=f"(r) : "f"(x)); return r;
}
__device__ __forceinline__ float fex2_a(float x) {
    float r; asm("ex2.approx.f32 %0, %1;" : "=f"(r) : "f"(x)); return r;
}
__device__ __forceinline__ float flg2_a(float x) {
    float r; asm("lg2.approx.f32 %0, %1;" : "=f"(r) : "f"(x)); return r;
}

// ---------------------------------------------------------------------------
// k_prep: corner-max -> g_M; counting-sort points by px -> g_spts.
// (Scatter order within a 1-px bucket is race-decided; the SET per bucket is
// deterministic, downstream sums are order-robust at ~1e-7.)
// ---------------------------------------------------------------------------
__global__ void k_prep(const float* __restrict__ pts) {
    __shared__ int   cnt[256], c2[256], offs[256];
    __shared__ float red[16];
    int t = threadIdx.x;                 // 512 threads
    float py = pts[2 * t], px = pts[2 * t + 1];

    float my = fmaxf(py, 255.0f - py);
    float mx = fmaxf(px, 255.0f - px);
    float lmax = fmaf(my, my, mx * mx);  // separable -> corner attains max
    for (int o = 16; o > 0; o >>= 1)
        lmax = fmaxf(lmax, __shfl_down_sync(0xffffffffu, lmax, o));
    if ((t & 31) == 0) red[t >> 5] = lmax;
    if (t < 256) { cnt[t] = 0; c2[t] = 0; }
    __syncthreads();
    if (t == 0) {
        float m = red[0];
#pragma unroll
        for (int i = 1; i < 16; ++i) m = fmaxf(m, red[i]);
        g_M = sqrtf(m);
    }
    int b = min(255, (int)px);
    atomicAdd(&cnt[b], 1);
    __syncthreads();
    if (t < 256) {                       // small one-time prefix sum
        int s = 0;
        for (int i = 0; i < t; ++i) s += cnt[i];
        offs[t] = s;
    }
    __syncthreads();
    int pos = offs[b] + atomicAdd(&c2[b], 1);
    g_spts[pos] = make_float2(px, py);
}

// ---------------------------------------------------------------------------
// k_all: 128 blocks x 1024 threads (one wave). Block b owns rows 2b, 2b+1.
//   phase A (exact): min-shift quadratic over all 512 points, +x^2 at end
//   phase B (windowed): point-major, px-sorted lanes -> tight warp x-window
//     (union of per-lane +-RW), paired MUFU rcp, exact dy recurrence.
// ---------------------------------------------------------------------------
__global__ __launch_bounds__(1024, 1) void k_all(const float* __restrict__ hm,
                                                 float* __restrict__ out) {
    __shared__ float4 preA[2][PP / 2];   // per row: (c1_0,c1_1,c0_0,c0_1)
    __shared__ float  s_hm[2][WW];       // per row: raw h
    __shared__ float4 s_hb[2][WW / 2];   // per row: (h0,h1,bb0,bb1)
    __shared__ float  s_min[2][2][256];  // per row, per point-half: shifted min
    __shared__ float  s_red[32], s_red2[32];

    int tid = threadIdx.x;               // 0..1023
    int row = tid >> 9;                  // 0/1 within the row pair
    int t   = tid & 511;                 // sorted-point index within row
    int y   = blockIdx.x * 2 + row;

    // ---- per-thread sorted point + per-row tables ---------------------------
    float2 sp = g_spts[t];
    float spx = sp.x, spy = sp.y;
    float dxv = (float)y - spy;
    float dxs = dxv * dxv;               // exact (y-py)^2
    {
        int cell = t >> 1, par = t & 1;
        float* pa = (float*)preA[row];
        pa[cell * 4 + par]     = -2.0f * spx;            // c1
        pa[cell * 4 + 2 + par] = fmaf(spx, spx, dxs);    // c0 = px^2 + dxs
    }
    float h = 0.f;
    if (t < WW) {
        h = hm[y * WW + t];
        s_hm[row][t] = h;
    }
    __syncthreads();
    if (t < WW / 2) {
        float M = g_M;
        float h0 = s_hm[row][2 * t], h1 = s_hm[row][2 * t + 1];
        s_hb[row][t] = make_float4(h0, h1, fmaf(-h0, M, M), fmaf(-h1, M, M));
    }
    __syncthreads();

    // ---------------- phase A: exact per-pixel min (shifted) -----------------
    int p  = tid & 255;                  // pixel
    int hp = (tid >> 8) & 1;             // point half
    {
        const float4* ptab = &preA[row][hp * 128];
        float xf = (float)p;
        float m0 = 3.4e38f, m1 = 3.4e38f;
#pragma unroll 8
        for (int k = 0; k < 128; ++k) {
            float4 qa = ptab[k];
            m0 = fminf(m0, fmaf(qa.x, xf, qa.z));
            m1 = fminf(m1, fmaf(qa.y, xf, qa.w));
        }
        s_min[row][hp][p] = fminf(m0, m1);
    }

    // ---------------- phase B: windowed soft-min power sums ------------------
    {
        int xl = (int)spx - RW;
        int xh = (int)spx + RW;
        for (int o = 16; o > 0; o >>= 1) {           // warp window union
            xl = min(xl, __shfl_xor_sync(0xffffffffu, xl, o));
            xh = max(xh, __shfl_xor_sync(0xffffffffu, xh, o));
        }
        xl = max(xl, 0) & ~1;
        xh = min(xh, 255);

        const float4* hb = s_hb[row];
        float dyA = (float)xl - spx;     // exact; += 2 recurrence stays exact
        float dyB = dyA + 1.0f;
        float accA = 0.f, accB = 0.f;
#pragma unroll 4
        for (int x2 = xl; x2 <= xh; x2 += 2) {
            float4 qb = hb[x2 >> 1];     // (h0,h1,bb0,bb1) broadcast LDS.128
            float sA = fmaf(dyA, dyA, dxs);
            float sB = fmaf(dyB, dyB, dxs);
            float dA = fsqrt_a(sA);      // MUFU sqrt x2
            float dB = fsqrt_a(sB);
            float wA = fmaf(qb.x, dA, qb.z);
            float wB = fmaf(qb.y, dB, qb.w);
            float r  = frcp_a(wA * wB);  // ONE MUFU rcp serves both pixels
            float qA = wB * r;
            float qB = wA * r;
            float qA2 = qA * qA, qB2 = qB * qB;
            accA = fmaf(qA2 * qA2, qA, accA);   // += w^-5
            accB = fmaf(qB2 * qB2, qB, accB);
            dyA += 2.0f;
            dyB += 2.0f;
        }
        atomicAdd(&g_sum[t], accA + accB);
    }
    __syncthreads();

    // ---------------- term-1 reduction (exact mins) --------------------------
    int warp = tid >> 5, lane = tid & 31;
    {
        float t1 = 0.f, ah = 0.f;
        if (hp == 0) {                   // these threads hold h for pixel p
            float xf2 = (float)p * (float)p;
            float mins = fminf(s_min[row][0][p], s_min[row][1][p]) + xf2;
            mins = fmaxf(mins, 0.0f);    // clamp cancellation error
            t1 = h * fsqrt_a(mins);
            ah = fabsf(h);
        }
        for (int o = 16; o > 0; o >>= 1) {
            t1 += __shfl_down_sync(0xffffffffu, t1, o);
            ah += __shfl_down_sync(0xffffffffu, ah, o);
        }
        if (lane == 0) { s_red[warp] = t1; s_red2[warp] = ah; }
    }
    __syncthreads();
    if (t == 0) {                        // one finisher per row
        int w0 = row * 16;               // row's hp==0 warps
        float a = 0.f, b = 0.f;
#pragma unroll
        for (int i = 0; i < 8; ++i) { a += s_red[w0 + i]; b += s_red2[w0 + i]; }
        g_numA[y] = a;
        g_denA[y] = b;
    }

    // ---------------- last-block epilogue ------------------------------------
    __shared__ int s_last;
    __threadfence();
    __syncthreads();
    if (tid == 0) s_last = (atomicAdd(&g_ctr, 1) == (int)gridDim.x - 1);
    __syncthreads();
    if (!s_last) return;

    float* red = (float*)preA;           // reuse smem
    float* r2  = (float*)s_hm;
    float* r3  = (float*)s_min;
    if (tid < PP) {
        float Ssum = g_sum[tid];
        red[tid] = fex2_a(-0.2f * flg2_a(Ssum * (1.0f / (HH * WW))));
        g_sum[tid] = 0.f;                // reset for next replay
    }
    if (tid < HH) { r2[tid] = g_numA[tid]; r3[tid] = g_denA[tid]; }
    __syncthreads();
    for (int o = 256; o > 0; o >>= 1) {
        if (tid < o) red[tid] += red[tid + o];
        __syncthreads();
    }
    for (int o = 128; o > 0; o >>= 1) {
        if (tid < o) { r2[tid] += r2[tid + o]; r3[tid] += r3[tid + o]; }
        __syncthreads();
    }
    if (tid == 0) {
        out[0] = r2[0] / r3[0] + red[0] * (1.0f / PP);
        g_ctr = 0;                       // reset for next replay
    }
}

extern "C" void kernel_launch(void* const* d_in, const int* in_sizes, int n_in,
                              void* d_out, int out_size) {
    (void)in_sizes; (void)n_in; (void)out_size;
    const float* hm  = (const float*)d_in[0];   // heat_map (256*256)
    const float* pts = (const float*)d_in[1];   // points   (512*2)
    float* out = (float*)d_out;

    k_prep<<<1, 512>>>(pts);
    k_all<<<HH / 2, 1024>>>(hm, out);
}